// round 14
// baseline (speedup 1.0000x reference)
#include <cuda_runtime.h>

typedef unsigned long long u64;

// ---------------- scratch (static device globals: allocation-free) ----------------
__device__ __align__(128) float g_k1t[4*8*4096*16];    // [b,h,s,d]
__device__ __align__(128) float g_v1t[4*8*4096*16];
__device__ __align__(128) float g_q1t[4*8*4096*16];
__device__ __align__(128) float g_k0t[4*8*16384*16];
__device__ __align__(128) float g_v0t[4*8*16384*16];
__device__ __align__(128) float g_q0t[4*8*16384*16];
__device__ __align__(128) float g_k2t[4*8*1024*16];
__device__ __align__(128) float g_v2t[4*8*1024*16];
__device__ __align__(128) float g_msg0[4*8*1024*16];       // [b,h,l,d]
__device__ __align__(128) float g_msg1[4*8*1024*4*16];     // [b,h,l,t,d]
__device__ int   g_idx0[4*8*1024*16];          // [b,h,l,16]
__device__ int   g_idx1[4*8*4096*8];           // [b,h,pix,8]

// ---------------- packed f32x2 helpers ----------------
__device__ __forceinline__ u64 pack2(float a, float b) {
    u64 r; asm("mov.b64 %0,{%1,%2};" : "=l"(r) : "f"(a), "f"(b)); return r;
}
__device__ __forceinline__ void unpack2(u64 v, float& a, float& b) {
    asm("mov.b64 {%0,%1},%2;" : "=f"(a), "=f"(b) : "l"(v));
}
__device__ __forceinline__ u64 ffma2(u64 a, u64 b, u64 c) {
    u64 d; asm("fma.rn.f32x2 %0,%1,%2,%3;" : "=l"(d) : "l"(a), "l"(b), "l"(c)); return d;
}
__device__ __forceinline__ u64 mul2(u64 a, u64 b) {
    u64 d; asm("mul.rn.f32x2 %0,%1,%2;" : "=l"(d) : "l"(a), "l"(b)); return d;
}
__device__ __forceinline__ u64 add2(u64 a, u64 b) {
    u64 d; asm("add.rn.f32x2 %0,%1,%2;" : "=l"(d) : "l"(a), "l"(b)); return d;
}

__device__ __forceinline__ void ld8(u64 (&r)[8], const float* p) {
    const ulonglong2* pp = reinterpret_cast<const ulonglong2*>(p);
    ulonglong2 a = pp[0], b = pp[1], c = pp[2], d = pp[3];
    r[0]=a.x; r[1]=a.y; r[2]=b.x; r[3]=b.y; r[4]=c.x; r[5]=c.y; r[6]=d.x; r[7]=d.y;
}

__device__ __forceinline__ float dot16u(const u64 (&qr)[8], const u64 (&k)[8]) {
    u64 d0 = mul2(qr[0],k[0]), d1 = mul2(qr[1],k[1]);
    u64 d2 = mul2(qr[2],k[2]), d3 = mul2(qr[3],k[3]);
    d0 = ffma2(qr[4],k[4],d0); d1 = ffma2(qr[5],k[5],d1);
    d2 = ffma2(qr[6],k[6],d2); d3 = ffma2(qr[7],k[7],d3);
    u64 e0 = add2(d0,d1), e1 = add2(d2,d3), e2 = add2(e0,e1);
    float lo, hi; unpack2(e2, lo, hi);
    return lo + hi;
}

__device__ __forceinline__ void acc_fma_u(u64 (&acc)[8], u64 e2, const u64 (&v)[8]) {
    #pragma unroll
    for (int i = 0; i < 8; ++i) acc[i] = ffma2(e2, v[i], acc[i]);
}

// branchless bubble insert into desc-sorted list (stable: ties keep earlier/lower idx)
template<int K>
__device__ __forceinline__ void bubble_insert(float (&tv)[K], int (&ti)[K], float sc, int id) {
    #pragma unroll
    for (int i = 0; i < K; ++i) {
        bool sw = sc > tv[i];
        float nv = sw ? tv[i] : sc;
        int   ni = sw ? ti[i] : id;
        tv[i] = sw ? sc : tv[i];
        ti[i] = sw ? id : ti[i];
        sc = nv; id = ni;
    }
}

__device__ __forceinline__ void topk_insert_tie(float (&tv)[16], int (&ti)[16], float sc, int id) {
    bool done = false;
    #pragma unroll
    for (int i = 15; i >= 1; --i) {
        if (!done) {
            bool beats = (sc > tv[i-1]) || (sc == tv[i-1] && id < ti[i-1]);
            if (beats) { tv[i] = tv[i-1]; ti[i] = ti[i-1]; }
            else       { tv[i] = sc; ti[i] = id; done = true; }
        }
    }
    if (!done) { tv[0] = sc; ti[0] = id; }
}

// ---------------- fused vectorized transpose: NCHW [b,128,S] -> [b,h,S,16] ----------------
__global__ __launch_bounds__(256) void k_transpose_all(
    const float* __restrict__ q0, const float* __restrict__ q1,
    const float* __restrict__ k0, const float* __restrict__ k1,
    const float* __restrict__ k2, const float* __restrict__ v0,
    const float* __restrict__ v1, const float* __restrict__ v2) {
    __shared__ __align__(16) float sm[16*132];
    int bid = blockIdx.x;
    const float* in; float* out; int S, lg2, local;
    if (bid < 256)        { in=k2; out=g_k2t; S=1024;  lg2=3; local=bid; }
    else if (bid < 512)   { in=v2; out=g_v2t; S=1024;  lg2=3; local=bid-256; }
    else if (bid < 1536)  { in=k1; out=g_k1t; S=4096;  lg2=5; local=bid-512; }
    else if (bid < 2560)  { in=v1; out=g_v1t; S=4096;  lg2=5; local=bid-1536; }
    else if (bid < 3584)  { in=q1; out=g_q1t; S=4096;  lg2=5; local=bid-2560; }
    else if (bid < 7680)  { in=k0; out=g_k0t; S=16384; lg2=7; local=bid-3584; }
    else if (bid < 11776) { in=v0; out=g_v0t; S=16384; lg2=7; local=bid-7680; }
    else                  { in=q0; out=g_q0t; S=16384; lg2=7; local=bid-11776; }
    const int bh = local >> lg2;
    const int s0 = (local & ((1 << lg2) - 1)) << 7;
    const int tid = threadIdx.x;
    const float* ib = in + ((size_t)bh * 16) * S + s0;
    #pragma unroll
    for (int k = 0; k < 2; ++k) {
        int fid = tid + k*256;
        int dd = fid >> 5, c4 = fid & 31;
        float4 v = *reinterpret_cast<const float4*>(ib + (size_t)dd*S + c4*4);
        *reinterpret_cast<float4*>(sm + dd*132 + c4*4) = v;
    }
    __syncthreads();
    float* ob = out + ((size_t)bh * S + s0) * 16;
    #pragma unroll
    for (int k = 0; k < 2; ++k) {
        int w = tid + k*256;
        int sl = w >> 2, d0 = (w & 3) << 2;
        float4 v;
        v.x = sm[(d0+0)*132 + sl];
        v.y = sm[(d0+1)*132 + sl];
        v.z = sm[(d0+2)*132 + sl];
        v.w = sm[(d0+3)*132 + sl];
        *reinterpret_cast<float4*>(ob + sl*16 + d0) = v;
    }
}

// ---------------- dummy (profiling alignment: level0 is 4th launch) ----------------
__global__ void k_dummy() {}

// ---------------- level 0: full attention 32x32, warp-split x8, broadcast LDG ----------------
__global__ __launch_bounds__(256) void k_level0(const float* __restrict__ q2) {
    __shared__ float sZ[8][32];
    __shared__ float sAcc[8][32][16];
    __shared__ float sTv[8][32][16];
    __shared__ short sTi[8][32][16];
    const int wid = threadIdx.x >> 5, lane = threadIdx.x & 31;
    const int bh = blockIdx.z * 8 + blockIdx.y;
    const int s = blockIdx.x * 32 + lane;

    const float* qb = q2 + (size_t)bh * 16 * 1024;
    u64 qr[8];
    #pragma unroll
    for (int i = 0; i < 8; ++i)
        qr[i] = pack2(qb[(2*i)*1024 + s], qb[(2*i+1)*1024 + s]);

    const float* kb = g_k2t + ((size_t)bh * 1024 + wid * 128) * 16;
    const float* vb = g_v2t + ((size_t)bh * 1024 + wid * 128) * 16;

    u64 acc[8];
    #pragma unroll
    for (int i = 0; i < 8; ++i) acc[i] = pack2(0.f, 0.f);
    float Z = 0.f;
    float topv[16]; int topi[16];
    #pragma unroll
    for (int i = 0; i < 16; ++i) { topv[i] = -1e30f; topi[i] = 0; }

    const int base = wid * 128;
    #pragma unroll 2
    for (int j = 0; j < 128; ++j) {
        u64 k8[8]; ld8(k8, kb + (size_t)j*16);          // uniform addr -> 1 line, L1-resident
        float sc = dot16u(qr, k8) * 0.25f;
        u64 v8[8]; ld8(v8, vb + (size_t)j*16);
        if (sc > topv[15]) bubble_insert<16>(topv, topi, sc, base + j);
        float e = __expf(sc);                            // |sc| small: no max-sub
        Z += e;
        acc_fma_u(acc, pack2(e, e), v8);
    }

    sZ[wid][lane] = Z;
    #pragma unroll
    for (int i = 0; i < 8; ++i) {
        float lo, hi; unpack2(acc[i], lo, hi);
        sAcc[wid][lane][2*i] = lo; sAcc[wid][lane][2*i+1] = hi;
    }
    #pragma unroll
    for (int r = 0; r < 16; ++r) { sTv[wid][lane][r] = topv[r]; sTi[wid][lane][r] = (short)topi[r]; }
    __syncthreads();

    if (wid == 0) {
        float Zt = 0.f, af[16];
        #pragma unroll
        for (int ch = 0; ch < 16; ++ch) af[ch] = 0.f;
        #pragma unroll
        for (int tt = 0; tt < 8; ++tt) {
            Zt += sZ[tt][lane];
            #pragma unroll
            for (int ch = 0; ch < 16; ++ch) af[ch] += sAcc[tt][lane][ch];
        }
        float tv[16]; int ti[16];
        #pragma unroll
        for (int i = 0; i < 16; ++i) { tv[i] = -1e30f; ti[i] = 0x7fffffff; }
        for (int tt = 0; tt < 8; ++tt) {
            for (int r = 0; r < 16; ++r) {
                float v = sTv[tt][lane][r]; int id = (int)sTi[tt][lane][r];
                bool beats = (v > tv[15]) || (v == tv[15] && id < ti[15]);
                if (beats) topk_insert_tie(tv, ti, v, id);
                else break;  // lists sorted desc (tie idx asc) -> monotone
            }
        }
        float inv = 1.f / Zt;
        float* mo = g_msg0 + ((size_t)bh*1024 + s)*16;
        #pragma unroll
        for (int ch = 0; ch < 16; ++ch) mo[ch] = af[ch] * inv;
        int* io = g_idx0 + ((size_t)bh*1024 + s)*16;
        #pragma unroll
        for (int r = 0; r < 16; ++r) io[r] = ti[r];
    }
}

// ============= level 1: smem-staged gather, 32 lists/block, 16 parent-chunks =============
__global__ __launch_bounds__(128) void k_level1() {
    __shared__ int sPar[32][16];
    __shared__ __align__(16) float sK[2][128*20];
    __shared__ __align__(16) float sV[2][128*20];
    const int tid = threadIdx.x;
    const int bh = blockIdx.z * 8 + blockIdx.y;
    const int lbase = blockIdx.x * 32;
    const int lg = tid >> 2, t = tid & 3;
    const int l = lbase + lg;

    #pragma unroll
    for (int k = 0; k < 4; ++k) {
        int id = tid + k*128;
        (&sPar[0][0])[id] = g_idx0[((size_t)bh*1024 + lbase + (id >> 4))*16 + (id & 15)];
    }

    const int ly = l >> 5, lx = l & 31;
    const int s1 = (2*ly + (t >> 1))*64 + 2*lx + (t & 1);
    u64 qr[8]; ld8(qr, g_q1t + ((size_t)bh*4096 + s1)*16);

    const float* kb = g_k1t + (size_t)bh * 4096 * 16;
    const float* vb = g_v1t + (size_t)bh * 4096 * 16;

    u64 acc[8];
    #pragma unroll
    for (int i = 0; i < 8; ++i) acc[i] = pack2(0.f, 0.f);
    float Z = 0.f;
    float topv[8]; int topi[8];
    #pragma unroll
    for (int i = 0; i < 8; ++i) { topv[i] = -1e30f; topi[i] = 0; }

    __syncthreads();

    #pragma unroll
    for (int k = 0; k < 8; ++k) {
        int sid = tid + k*128;
        int row = sid >> 2, sseg = sid & 3;
        int r = row & 127;
        int c = r >> 5, lst = r & 31;
        int p = sPar[lst][0];
        int cand = (((p >> 5) << 1) + (c >> 1))*64 + ((p & 31) << 1) + (c & 1);
        const float* src = (row < 128 ? kb : vb) + ((size_t)cand*16 + sseg*4);
        float* dst = (row < 128 ? sK[0] : sV[0]) + r*20 + sseg*4;
        *reinterpret_cast<float4*>(dst) = *reinterpret_cast<const float4*>(src);
    }

    for (int w = 0; w < 16; ++w) {
        __syncthreads();
        int buf = w & 1;
        if (w + 1 < 16) {
            int nb = (w + 1) & 1;
            #pragma unroll
            for (int k = 0; k < 8; ++k) {
                int sid = tid + k*128;
                int row = sid >> 2, sseg = sid & 3;
                int r = row & 127;
                int c = r >> 5, lst = r & 31;
                int p = sPar[lst][w + 1];
                int cand = (((p >> 5) << 1) + (c >> 1))*64 + ((p & 31) << 1) + (c & 1);
                const float* src = (row < 128 ? kb : vb) + ((size_t)cand*16 + sseg*4);
                float* dst = (row < 128 ? sK[nb] : sV[nb]) + r*20 + sseg*4;
                *reinterpret_cast<float4*>(dst) = *reinterpret_cast<const float4*>(src);
            }
        }
        #pragma unroll
        for (int c = 0; c < 4; ++c) {
            int r = c*32 + lg;
            u64 k8[8]; ld8(k8, sK[buf] + r*20);
            float sc = dot16u(qr, k8) * 0.25f;
            u64 v8[8]; ld8(v8, sV[buf] + r*20);
            if (sc > topv[7]) bubble_insert<8>(topv, topi, sc, w*4 + c);
            float e = __expf(sc);
            Z += e;
            acc_fma_u(acc, pack2(e, e), v8);
        }
    }

    float inv = 1.f / Z;
    u64 i2 = pack2(inv, inv);
    float* mo = g_msg1 + (((size_t)bh*1024 + l)*4 + t)*16;
    #pragma unroll
    for (int i = 0; i < 8; ++i) {
        float lo, hi; unpack2(mul2(acc[i], i2), lo, hi);
        mo[2*i] = lo; mo[2*i+1] = hi;
    }
    int* io = g_idx1 + ((size_t)bh*4096 + s1)*8;
    #pragma unroll
    for (int r = 0; r < 8; ++r) {
        int slot = topi[r];
        int p = sPar[lg][slot >> 2];
        int c = slot & 3;
        io[r] = (((p >> 5) << 1) + (c >> 1))*64 + ((p & 31) << 1) + (c & 1);
    }
}

// ===== level 2 + combine fused: smem-staged gather, 32 lists/block, 8 chunks; writes final out =====
__global__ __launch_bounds__(128) void k_level2(const float* __restrict__ wt, float* __restrict__ out) {
    __shared__ int sPar[32][8];
    __shared__ __align__(16) float sK[2][128*20];
    __shared__ __align__(16) float sV[2][128*20];
    const int tid = threadIdx.x;
    const int bh = blockIdx.z * 8 + blockIdx.y;
    const int lbase = blockIdx.x * 32;
    const int lg = tid >> 2, t = tid & 3;
    const int l = lbase + lg;

    #pragma unroll
    for (int k = 0; k < 2; ++k) {
        int id = tid + k*128;
        (&sPar[0][0])[id] = g_idx1[((size_t)bh*4096 + lbase + (id >> 3))*8 + (id & 7)];
    }

    const int ly = l >> 6, lx = l & 63;
    const int y = 2*ly + (t >> 1), x = 2*lx + (t & 1);
    const int s0 = y*128 + x;
    u64 qr[8]; ld8(qr, g_q0t + ((size_t)bh*16384 + s0)*16);

    const float* kb = g_k0t + (size_t)bh * 16384 * 16;
    const float* vb = g_v0t + (size_t)bh * 16384 * 16;

    u64 acc[8];
    #pragma unroll
    for (int i = 0; i < 8; ++i) acc[i] = pack2(0.f, 0.f);
    float Z = 0.f;

    __syncthreads();

    #pragma unroll
    for (int k = 0; k < 8; ++k) {
        int sid = tid + k*128;
        int row = sid >> 2, sseg = sid & 3;
        int r = row & 127;
        int c = r >> 5, lst = r & 31;
        int p = sPar[lst][0];
        int cand = (((p >> 6) << 1) + (c >> 1))*128 + ((p & 63) << 1) + (c & 1);
        const float* src = (row < 128 ? kb : vb) + ((size_t)cand*16 + sseg*4);
        float* dst = (row < 128 ? sK[0] : sV[0]) + r*20 + sseg*4;
        *reinterpret_cast<float4*>(dst) = *reinterpret_cast<const float4*>(src);
    }

    for (int w = 0; w < 8; ++w) {
        __syncthreads();
        int buf = w & 1;
        if (w + 1 < 8) {
            int nb = (w + 1) & 1;
            #pragma unroll
            for (int k = 0; k < 8; ++k) {
                int sid = tid + k*128;
                int row = sid >> 2, sseg = sid & 3;
                int r = row & 127;
                int c = r >> 5, lst = r & 31;
                int p = sPar[lst][w + 1];
                int cand = (((p >> 6) << 1) + (c >> 1))*128 + ((p & 63) << 1) + (c & 1);
                const float* src = (row < 128 ? kb : vb) + ((size_t)cand*16 + sseg*4);
                float* dst = (row < 128 ? sK[nb] : sV[nb]) + r*20 + sseg*4;
                *reinterpret_cast<float4*>(dst) = *reinterpret_cast<const float4*>(src);
            }
        }
        #pragma unroll
        for (int c = 0; c < 4; ++c) {
            int r = c*32 + lg;
            u64 k8[8]; ld8(k8, sK[buf] + r*20);
            float sc = dot16u(qr, k8) * 0.25f;
            u64 v8[8]; ld8(v8, sV[buf] + r*20);
            float e = __expf(sc);
            Z += e;
            acc_fma_u(acc, pack2(e, e), v8);
        }
    }

    // ---- fused combine: out = w0*msg0[l0] + w1*msg1[l0,t1] + w2*(acc/Z) ----
    float w0r = wt[0], w1r = wt[1], w2r = wt[2];
    float mx = fmaxf(w0r, fmaxf(w1r, w2r));
    float e0 = __expf(w0r - mx), e1 = __expf(w1r - mx), e2 = __expf(w2r - mx);
    float winv = 1.f / (e0 + e1 + e2);
    float w0 = e0*winv, w1 = e1*winv, w2 = e2*winv;

    const int l0 = (ly >> 1)*32 + (lx >> 1);
    const int t1 = ((ly & 1) << 1) | (lx & 1);
    u64 m0[8]; ld8(m0, g_msg0 + ((size_t)bh*1024 + l0)*16);
    u64 m1[8]; ld8(m1, g_msg1 + (((size_t)bh*1024 + l0)*4 + t1)*16);

    float w2z = w2 / Z;
    u64 w0_2 = pack2(w0, w0), w1_2 = pack2(w1, w1), w2z2 = pack2(w2z, w2z);
    const int b = bh >> 3, h = bh & 7;
    float* po = out + ((size_t)((b*16384 + s0)*8 + h))*16;
    #pragma unroll
    for (int i = 0; i < 8; ++i) {
        u64 r = mul2(acc[i], w2z2);
        r = ffma2(w1_2, m1[i], r);
        r = ffma2(w0_2, m0[i], r);
        float lo, hi; unpack2(r, lo, hi);
        po[2*i] = lo; po[2*i+1] = hi;
    }
}

// ---------------- launcher ----------------
extern "C" void kernel_launch(void* const* d_in, const int* in_sizes, int n_in,
                              void* d_out, int out_size) {
    (void)in_sizes; (void)n_in; (void)out_size;
    const float* q0 = (const float*)d_in[0];
    const float* q1 = (const float*)d_in[1];
    const float* q2 = (const float*)d_in[2];
    const float* k0 = (const float*)d_in[3];
    const float* k1 = (const float*)d_in[4];
    const float* k2 = (const float*)d_in[5];
    const float* v0 = (const float*)d_in[6];
    const float* v1 = (const float*)d_in[7];
    const float* v2 = (const float*)d_in[8];
    const float* wt = (const float*)d_in[9];
    float* out = (float*)d_out;

    k_transpose_all<<<15872, 256>>>(q0, q1, k0, k1, k2, v0, v1, v2);
    k_dummy<<<1, 32>>>();
    k_dummy<<<1, 32>>>();                           // level0 = 4th launch -> ncu capture
    k_level0<<<dim3(32,  8, 4), 256>>>(q2);
    k_level1<<<dim3(32,  8, 4), 128>>>();
    k_level2<<<dim3(128, 8, 4), 128>>>(wt, out);
}

// round 16
// speedup vs baseline: 1.1845x; 1.1845x over previous
#include <cuda_runtime.h>

typedef unsigned long long u64;

// ---------------- scratch (static device globals: allocation-free) ----------------
__device__ __align__(128) float g_k1t[4*8*4096*16];    // [b,h,s,d]
__device__ __align__(128) float g_v1t[4*8*4096*16];
__device__ __align__(128) float g_q1t[4*8*4096*16];
__device__ __align__(128) float g_k0t[4*8*16384*16];
__device__ __align__(128) float g_v0t[4*8*16384*16];
__device__ __align__(128) float g_q0t[4*8*16384*16];
__device__ __align__(128) float g_k2t[4*8*1024*16];
__device__ __align__(128) float g_v2t[4*8*1024*16];
__device__ __align__(128) float g_msg0[4*8*1024*16];       // [b,h,l,d]
__device__ __align__(128) float g_msg1[4*8*1024*4*16];     // [b,h,l,t,d]
__device__ __align__(128) float g_scores[4*8*1024*1024];   // [bh][j][q]  128MB
__device__ int   g_idx0[4*8*1024*16];          // [b,h,l,16]
__device__ int   g_idx1[4*8*4096*8];           // [b,h,pix,8]

// ---------------- packed f32x2 helpers ----------------
__device__ __forceinline__ u64 pack2(float a, float b) {
    u64 r; asm("mov.b64 %0,{%1,%2};" : "=l"(r) : "f"(a), "f"(b)); return r;
}
__device__ __forceinline__ void unpack2(u64 v, float& a, float& b) {
    asm("mov.b64 {%0,%1},%2;" : "=f"(a), "=f"(b) : "l"(v));
}
__device__ __forceinline__ u64 ffma2(u64 a, u64 b, u64 c) {
    u64 d; asm("fma.rn.f32x2 %0,%1,%2,%3;" : "=l"(d) : "l"(a), "l"(b), "l"(c)); return d;
}
__device__ __forceinline__ u64 mul2(u64 a, u64 b) {
    u64 d; asm("mul.rn.f32x2 %0,%1,%2;" : "=l"(d) : "l"(a), "l"(b)); return d;
}
__device__ __forceinline__ u64 add2(u64 a, u64 b) {
    u64 d; asm("add.rn.f32x2 %0,%1,%2;" : "=l"(d) : "l"(a), "l"(b)); return d;
}

__device__ __forceinline__ void ld8(u64 (&r)[8], const float* p) {
    const ulonglong2* pp = reinterpret_cast<const ulonglong2*>(p);
    ulonglong2 a = pp[0], b = pp[1], c = pp[2], d = pp[3];
    r[0]=a.x; r[1]=a.y; r[2]=b.x; r[3]=b.y; r[4]=c.x; r[5]=c.y; r[6]=d.x; r[7]=d.y;
}

__device__ __forceinline__ float dot16u(const u64 (&qr)[8], const u64 (&k)[8]) {
    u64 d0 = mul2(qr[0],k[0]), d1 = mul2(qr[1],k[1]);
    u64 d2 = mul2(qr[2],k[2]), d3 = mul2(qr[3],k[3]);
    d0 = ffma2(qr[4],k[4],d0); d1 = ffma2(qr[5],k[5],d1);
    d2 = ffma2(qr[6],k[6],d2); d3 = ffma2(qr[7],k[7],d3);
    u64 e0 = add2(d0,d1), e1 = add2(d2,d3), e2 = add2(e0,e1);
    float lo, hi; unpack2(e2, lo, hi);
    return lo + hi;
}

__device__ __forceinline__ void acc_fma_u(u64 (&acc)[8], u64 e2, const u64 (&v)[8]) {
    #pragma unroll
    for (int i = 0; i < 8; ++i) acc[i] = ffma2(e2, v[i], acc[i]);
}

// branchless bubble insert into desc-sorted list (stable: ties keep earlier/lower idx)
template<int K>
__device__ __forceinline__ void bubble_insert(float (&tv)[K], int (&ti)[K], float sc, int id) {
    #pragma unroll
    for (int i = 0; i < K; ++i) {
        bool sw = sc > tv[i];
        float nv = sw ? tv[i] : sc;
        int   ni = sw ? ti[i] : id;
        tv[i] = sw ? sc : tv[i];
        ti[i] = sw ? id : ti[i];
        sc = nv; id = ni;
    }
}

// ---------------- fused vectorized transpose: NCHW [b,128,S] -> [b,h,S,16] ----------------
__global__ __launch_bounds__(256) void k_transpose_all(
    const float* __restrict__ q0, const float* __restrict__ q1,
    const float* __restrict__ k0, const float* __restrict__ k1,
    const float* __restrict__ k2, const float* __restrict__ v0,
    const float* __restrict__ v1, const float* __restrict__ v2) {
    __shared__ __align__(16) float sm[16*132];
    int bid = blockIdx.x;
    const float* in; float* out; int S, lg2, local;
    if (bid < 256)        { in=k2; out=g_k2t; S=1024;  lg2=3; local=bid; }
    else if (bid < 512)   { in=v2; out=g_v2t; S=1024;  lg2=3; local=bid-256; }
    else if (bid < 1536)  { in=k1; out=g_k1t; S=4096;  lg2=5; local=bid-512; }
    else if (bid < 2560)  { in=v1; out=g_v1t; S=4096;  lg2=5; local=bid-1536; }
    else if (bid < 3584)  { in=q1; out=g_q1t; S=4096;  lg2=5; local=bid-2560; }
    else if (bid < 7680)  { in=k0; out=g_k0t; S=16384; lg2=7; local=bid-3584; }
    else if (bid < 11776) { in=v0; out=g_v0t; S=16384; lg2=7; local=bid-7680; }
    else                  { in=q0; out=g_q0t; S=16384; lg2=7; local=bid-11776; }
    const int bh = local >> lg2;
    const int s0 = (local & ((1 << lg2) - 1)) << 7;
    const int tid = threadIdx.x;
    const float* ib = in + ((size_t)bh * 16) * S + s0;
    #pragma unroll
    for (int k = 0; k < 2; ++k) {
        int fid = tid + k*256;
        int dd = fid >> 5, c4 = fid & 31;
        float4 v = *reinterpret_cast<const float4*>(ib + (size_t)dd*S + c4*4);
        *reinterpret_cast<float4*>(sm + dd*132 + c4*4) = v;
    }
    __syncthreads();
    float* ob = out + ((size_t)bh * S + s0) * 16;
    #pragma unroll
    for (int k = 0; k < 2; ++k) {
        int w = tid + k*256;
        int sl = w >> 2, d0 = (w & 3) << 2;
        float4 v;
        v.x = sm[(d0+0)*132 + sl];
        v.y = sm[(d0+1)*132 + sl];
        v.z = sm[(d0+2)*132 + sl];
        v.w = sm[(d0+3)*132 + sl];
        *reinterpret_cast<float4*>(ob + sl*16 + d0) = v;
    }
}

// ---------------- dummy (profiling alignment) ----------------
__global__ void k_dummy() {}

// ======== level 0 Phase A: scores + softmax accumulate (no selection) ========
__global__ __launch_bounds__(256) void k_score0(const float* __restrict__ q2) {
    __shared__ float sZ[8][32];
    __shared__ float sAcc[8][32][16];
    const int wid = threadIdx.x >> 5, lane = threadIdx.x & 31;
    const int bh = blockIdx.z * 8 + blockIdx.y;
    const int s = blockIdx.x * 32 + lane;

    const float* qb = q2 + (size_t)bh * 16 * 1024;
    u64 qr[8];
    #pragma unroll
    for (int i = 0; i < 8; ++i)
        qr[i] = pack2(qb[(2*i)*1024 + s], qb[(2*i+1)*1024 + s]);

    const float* kb = g_k2t + ((size_t)bh * 1024 + wid * 128) * 16;
    const float* vb = g_v2t + ((size_t)bh * 1024 + wid * 128) * 16;
    float* sco = g_scores + ((size_t)bh*1024 + wid*128)*1024 + blockIdx.x*32 + lane;

    u64 acc[8];
    #pragma unroll
    for (int i = 0; i < 8; ++i) acc[i] = pack2(0.f, 0.f);
    float Z = 0.f;

    #pragma unroll 4
    for (int j = 0; j < 128; ++j) {
        u64 k8[8]; ld8(k8, kb + (size_t)j*16);          // uniform addr -> broadcast, 1 line
        float sc = dot16u(qr, k8) * 0.25f;
        u64 v8[8]; ld8(v8, vb + (size_t)j*16);
        sco[j << 10] = sc;                               // lanes consecutive q -> 1 line
        float e = __expf(sc);                            // |sc| small: no max-sub
        Z += e;
        acc_fma_u(acc, pack2(e, e), v8);
    }

    sZ[wid][lane] = Z;
    #pragma unroll
    for (int i = 0; i < 8; ++i) {
        float lo, hi; unpack2(acc[i], lo, hi);
        sAcc[wid][lane][2*i] = lo; sAcc[wid][lane][2*i+1] = hi;
    }
    __syncthreads();

    if (wid == 0) {
        float Zt = 0.f, af[16];
        #pragma unroll
        for (int ch = 0; ch < 16; ++ch) af[ch] = 0.f;
        #pragma unroll
        for (int tt = 0; tt < 8; ++tt) {
            Zt += sZ[tt][lane];
            #pragma unroll
            for (int ch = 0; ch < 16; ++ch) af[ch] += sAcc[tt][lane][ch];
        }
        float inv = 1.f / Zt;
        float* mo = g_msg0 + ((size_t)bh*1024 + s)*16;
        #pragma unroll
        for (int ch = 0; ch < 16; ++ch) mo[ch] = af[ch] * inv;
    }
}

// ======== level 0 Phase B: exact top-16 per query, warp-per-query ========
// block: 512 thr = 16 warps = 16 queries; smem: 16 rows of 1033 floats (odd stride)
extern __shared__ float sS[];
__global__ __launch_bounds__(512) void k_top0() {
    const int tid = threadIdx.x;
    const int w = tid >> 5, lane = tid & 31;
    const int bh = blockIdx.z * 8 + blockIdx.y;
    const int qbase = blockIdx.x * 16;

    // cooperative transposed load: sS[ql*1033 + j] = scores[bh][j][qbase+ql]
    {
        const int ql = tid & 15, jj = tid >> 4;         // jj in [0,32)
        const float* src = g_scores + ((size_t)bh*1024 + jj*32)*1024 + qbase + ql;
        float* dst = sS + ql*1033 + jj*32;
        #pragma unroll
        for (int i = 0; i < 32; ++i)
            dst[i] = src[(size_t)i << 10];
    }
    __syncthreads();

    const float* row = sS + w*1033;

    // per-lane top-2 cache over keys j = i*32+lane, ascending j (stable ties)
    float c0 = -1e30f, c1 = -1e30f; int i0 = 0x7fffffff, i1 = 0x7fffffff;
    #pragma unroll
    for (int i = 0; i < 32; ++i) {
        float v = row[i*32 + lane];
        int j = i*32 + lane;
        bool sw0 = v > c0;
        float tv = sw0 ? c0 : v; int tj = sw0 ? i0 : j;
        c0 = sw0 ? v : c0; i0 = sw0 ? j : i0;
        bool sw1 = tv > c1;
        c1 = sw1 ? tv : c1; i1 = sw1 ? tj : i1;
    }

    float hv = c0; int hj = i0;         // lane head
    float lv = 0.f; int lj = 0;         // last consumed (valid when cnt>=1)
    int cnt = 0;
    int outj = 0;

    for (int r = 0; r < 16; ++r) {
        // warp argmax by (value desc, index asc)
        float wv = hv; int wj = hj;
        #pragma unroll
        for (int m = 16; m; m >>= 1) {
            float ov = __shfl_xor_sync(0xffffffffu, wv, m);
            int   oj = __shfl_xor_sync(0xffffffffu, wj, m);
            if (ov > wv || (ov == wv && oj < wj)) { wv = ov; wj = oj; }
        }
        if (lane == r) outj = wj;
        if ((wj & 31) == lane) {        // this lane owns the winner: advance head
            lv = hv; lj = hj;
            ++cnt;
            if (cnt == 1) { hv = c1; hj = i1; }
            else {
                // rescan: max element strictly after (lv,lj) in total order
                float bv = -1e30f; int bj = 0x7fffffff;
                for (int i = 0; i < 32; ++i) {
                    float v = row[i*32 + lane];
                    int j = i*32 + lane;
                    bool after  = (v < lv) || (v == lv && j > lj);
                    bool better = after && ((v > bv) || (v == bv && j < bj));
                    bv = better ? v : bv; bj = better ? j : bj;
                }
                hv = bv; hj = bj;
            }
        }
    }
    if (lane < 16)
        g_idx0[((size_t)bh*1024 + qbase + w)*16 + lane] = outj;
}

// ============= level 1: smem-staged gather, 32 lists/block, 16 parent-chunks =============
__global__ __launch_bounds__(128) void k_level1() {
    __shared__ int sPar[32][16];
    __shared__ __align__(16) float sK[2][128*20];
    __shared__ __align__(16) float sV[2][128*20];
    const int tid = threadIdx.x;
    const int bh = blockIdx.z * 8 + blockIdx.y;
    const int lbase = blockIdx.x * 32;
    const int lg = tid >> 2, t = tid & 3;
    const int l = lbase + lg;

    #pragma unroll
    for (int k = 0; k < 4; ++k) {
        int id = tid + k*128;
        (&sPar[0][0])[id] = g_idx0[((size_t)bh*1024 + lbase + (id >> 4))*16 + (id & 15)];
    }

    const int ly = l >> 5, lx = l & 31;
    const int s1 = (2*ly + (t >> 1))*64 + 2*lx + (t & 1);
    u64 qr[8]; ld8(qr, g_q1t + ((size_t)bh*4096 + s1)*16);

    const float* kb = g_k1t + (size_t)bh * 4096 * 16;
    const float* vb = g_v1t + (size_t)bh * 4096 * 16;

    u64 acc[8];
    #pragma unroll
    for (int i = 0; i < 8; ++i) acc[i] = pack2(0.f, 0.f);
    float Z = 0.f;
    float topv[8]; int topi[8];
    #pragma unroll
    for (int i = 0; i < 8; ++i) { topv[i] = -1e30f; topi[i] = 0; }

    __syncthreads();

    #pragma unroll
    for (int k = 0; k < 8; ++k) {
        int sid = tid + k*128;
        int row = sid >> 2, sseg = sid & 3;
        int r = row & 127;
        int c = r >> 5, lst = r & 31;
        int p = sPar[lst][0];
        int cand = (((p >> 5) << 1) + (c >> 1))*64 + ((p & 31) << 1) + (c & 1);
        const float* src = (row < 128 ? kb : vb) + ((size_t)cand*16 + sseg*4);
        float* dst = (row < 128 ? sK[0] : sV[0]) + r*20 + sseg*4;
        *reinterpret_cast<float4*>(dst) = *reinterpret_cast<const float4*>(src);
    }

    for (int w = 0; w < 16; ++w) {
        __syncthreads();
        int buf = w & 1;
        if (w + 1 < 16) {
            int nb = (w + 1) & 1;
            #pragma unroll
            for (int k = 0; k < 8; ++k) {
                int sid = tid + k*128;
                int row = sid >> 2, sseg = sid & 3;
                int r = row & 127;
                int c = r >> 5, lst = r & 31;
                int p = sPar[lst][w + 1];
                int cand = (((p >> 5) << 1) + (c >> 1))*64 + ((p & 31) << 1) + (c & 1);
                const float* src = (row < 128 ? kb : vb) + ((size_t)cand*16 + sseg*4);
                float* dst = (row < 128 ? sK[nb] : sV[nb]) + r*20 + sseg*4;
                *reinterpret_cast<float4*>(dst) = *reinterpret_cast<const float4*>(src);
            }
        }
        #pragma unroll
        for (int c = 0; c < 4; ++c) {
            int r = c*32 + lg;
            u64 k8[8]; ld8(k8, sK[buf] + r*20);
            float sc = dot16u(qr, k8) * 0.25f;
            u64 v8[8]; ld8(v8, sV[buf] + r*20);
            if (sc > topv[7]) bubble_insert<8>(topv, topi, sc, w*4 + c);
            float e = __expf(sc);
            Z += e;
            acc_fma_u(acc, pack2(e, e), v8);
        }
    }

    float inv = 1.f / Z;
    u64 i2 = pack2(inv, inv);
    float* mo = g_msg1 + (((size_t)bh*1024 + l)*4 + t)*16;
    #pragma unroll
    for (int i = 0; i < 8; ++i) {
        float lo, hi; unpack2(mul2(acc[i], i2), lo, hi);
        mo[2*i] = lo; mo[2*i+1] = hi;
    }
    int* io = g_idx1 + ((size_t)bh*4096 + s1)*8;
    #pragma unroll
    for (int r = 0; r < 8; ++r) {
        int slot = topi[r];
        int p = sPar[lg][slot >> 2];
        int c = slot & 3;
        io[r] = (((p >> 5) << 1) + (c >> 1))*64 + ((p & 31) << 1) + (c & 1);
    }
}

// ===== level 2 + combine fused: smem-staged gather, 32 lists/block, 8 chunks =====
__global__ __launch_bounds__(128) void k_level2(const float* __restrict__ wt, float* __restrict__ out) {
    __shared__ int sPar[32][8];
    __shared__ __align__(16) float sK[2][128*20];
    __shared__ __align__(16) float sV[2][128*20];
    const int tid = threadIdx.x;
    const int bh = blockIdx.z * 8 + blockIdx.y;
    const int lbase = blockIdx.x * 32;
    const int lg = tid >> 2, t = tid & 3;
    const int l = lbase + lg;

    #pragma unroll
    for (int k = 0; k < 2; ++k) {
        int id = tid + k*128;
        (&sPar[0][0])[id] = g_idx1[((size_t)bh*4096 + lbase + (id >> 3))*8 + (id & 7)];
    }

    const int ly = l >> 6, lx = l & 63;
    const int y = 2*ly + (t >> 1), x = 2*lx + (t & 1);
    const int s0 = y*128 + x;
    u64 qr[8]; ld8(qr, g_q0t + ((size_t)bh*16384 + s0)*16);

    const float* kb = g_k0t + (size_t)bh * 16384 * 16;
    const float* vb = g_v0t + (size_t)bh * 16384 * 16;

    u64 acc[8];
    #pragma unroll
    for (int i = 0; i < 8; ++i) acc[i] = pack2(0.f, 0.f);
    float Z = 0.f;

    __syncthreads();

    #pragma unroll
    for (int k = 0; k < 8; ++k) {
        int sid = tid + k*128;
        int row = sid >> 2, sseg = sid & 3;
        int r = row & 127;
        int c = r >> 5, lst = r & 31;
        int p = sPar[lst][0];
        int cand = (((p >> 6) << 1) + (c >> 1))*128 + ((p & 63) << 1) + (c & 1);
        const float* src = (row < 128 ? kb : vb) + ((size_t)cand*16 + sseg*4);
        float* dst = (row < 128 ? sK[0] : sV[0]) + r*20 + sseg*4;
        *reinterpret_cast<float4*>(dst) = *reinterpret_cast<const float4*>(src);
    }

    for (int w = 0; w < 8; ++w) {
        __syncthreads();
        int buf = w & 1;
        if (w + 1 < 8) {
            int nb = (w + 1) & 1;
            #pragma unroll
            for (int k = 0; k < 8; ++k) {
                int sid = tid + k*128;
                int row = sid >> 2, sseg = sid & 3;
                int r = row & 127;
                int c = r >> 5, lst = r & 31;
                int p = sPar[lst][w + 1];
                int cand = (((p >> 6) << 1) + (c >> 1))*128 + ((p & 63) << 1) + (c & 1);
                const float* src = (row < 128 ? kb : vb) + ((size_t)cand*16 + sseg*4);
                float* dst = (row < 128 ? sK[nb] : sV[nb]) + r*20 + sseg*4;
                *reinterpret_cast<float4*>(dst) = *reinterpret_cast<const float4*>(src);
            }
        }
        #pragma unroll
        for (int c = 0; c < 4; ++c) {
            int r = c*32 + lg;
            u64 k8[8]; ld8(k8, sK[buf] + r*20);
            float sc = dot16u(qr, k8) * 0.25f;
            u64 v8[8]; ld8(v8, sV[buf] + r*20);
            float e = __expf(sc);
            Z += e;
            acc_fma_u(acc, pack2(e, e), v8);
        }
    }

    // fused combine
    float w0r = wt[0], w1r = wt[1], w2r = wt[2];
    float mx = fmaxf(w0r, fmaxf(w1r, w2r));
    float e0 = __expf(w0r - mx), e1 = __expf(w1r - mx), e2 = __expf(w2r - mx);
    float winv = 1.f / (e0 + e1 + e2);
    float w0 = e0*winv, w1 = e1*winv, w2 = e2*winv;

    const int l0 = (ly >> 1)*32 + (lx >> 1);
    const int t1 = ((ly & 1) << 1) | (lx & 1);
    u64 m0[8]; ld8(m0, g_msg0 + ((size_t)bh*1024 + l0)*16);
    u64 m1[8]; ld8(m1, g_msg1 + (((size_t)bh*1024 + l0)*4 + t1)*16);

    float w2z = w2 / Z;
    u64 w0_2 = pack2(w0, w0), w1_2 = pack2(w1, w1), w2z2 = pack2(w2z, w2z);
    const int b = bh >> 3, h = bh & 7;
    float* po = out + ((size_t)((b*16384 + s0)*8 + h))*16;
    #pragma unroll
    for (int i = 0; i < 8; ++i) {
        u64 r = mul2(acc[i], w2z2);
        r = ffma2(w1_2, m1[i], r);
        r = ffma2(w0_2, m0[i], r);
        float lo, hi; unpack2(r, lo, hi);
        po[2*i] = lo; po[2*i+1] = hi;
    }
}

// ---------------- launcher ----------------
extern "C" void kernel_launch(void* const* d_in, const int* in_sizes, int n_in,
                              void* d_out, int out_size) {
    (void)in_sizes; (void)n_in; (void)out_size;
    const float* q0 = (const float*)d_in[0];
    const float* q1 = (const float*)d_in[1];
    const float* q2 = (const float*)d_in[2];
    const float* k0 = (const float*)d_in[3];
    const float* k1 = (const float*)d_in[4];
    const float* k2 = (const float*)d_in[5];
    const float* v0 = (const float*)d_in[6];
    const float* v1 = (const float*)d_in[7];
    const float* v2 = (const float*)d_in[8];
    const float* wt = (const float*)d_in[9];
    float* out = (float*)d_out;

    cudaFuncSetAttribute(k_top0, cudaFuncAttributeMaxDynamicSharedMemorySize, 16*1033*4);

    k_transpose_all<<<15872, 256>>>(q0, q1, k0, k1, k2, v0, v1, v2);
    k_score0<<<dim3(32, 8, 4), 256>>>(q2);
    k_dummy<<<1, 32>>>();                               // k_top0 = 4th launch -> ncu capture
    k_top0<<<dim3(64, 8, 4), 512, 16*1033*4>>>();
    k_level1<<<dim3(32, 8, 4), 128>>>();
    k_level2<<<dim3(128, 8, 4), 128>>>(wt, out);
}